// round 15
// baseline (speedup 1.0000x reference)
#include <cuda_runtime.h>
#include <cuda_fp16.h>
#include <cstdint>

// ENC_GRUTurbo: fused 2-layer minGRU x2 nets + global standardize.
// B=256, L=2048, H=64. One CTA per (batch, net).
// R15 = R12 body with f32x2-packed scans (2 channels/instr, bit-identical),
// composites as ulonglong2, gate/bias/wo constants hoisted to registers.

#define BB 256
#define LL 2048
#define HH 64
#define TT 64
#define NC (LL / TT)
#define NTOT (BB * LL * 2)

typedef unsigned long long ull;

__device__ float2 g_part[BB * 2];
__device__ float g_mean_f, g_rstd_f;
__device__ unsigned int g_done;   // reset to 0 by last CTA each launch

__device__ __forceinline__ uint32_t smem_u32(const void* p) {
    uint32_t a;
    asm("{ .reg .u64 t; cvta.to.shared.u64 t, %1; cvt.u32.u64 %0, t; }"
        : "=r"(a) : "l"(p));
    return a;
}
__device__ __forceinline__ float sigmoidf(float x) {       // precise (init only)
    return 1.0f / (1.0f + __expf(-x));
}
__device__ __forceinline__ float tanh_fast(float x) {      // hot path
    float t;
    asm("tanh.approx.f32 %0, %1;" : "=f"(t) : "f"(x));
    return t;
}
__device__ __forceinline__ ull fma2(ull a, ull b, ull c) {
    ull d;
    asm("fma.rn.f32x2 %0, %1, %2, %3;" : "=l"(d) : "l"(a), "l"(b), "l"(c));
    return d;
}
__device__ __forceinline__ ull mul2(ull a, ull b) {
    ull d;
    asm("mul.rn.f32x2 %0, %1, %2;" : "=l"(d) : "l"(a), "l"(b));
    return d;
}
__device__ __forceinline__ ull pack2(float x, float y) {
    ull d;
    asm("mov.b64 %0, {%1, %2};" : "=l"(d) : "f"(x), "f"(y));
    return d;
}
__device__ __forceinline__ float2 unpack2(ull v) {
    float x, y;
    asm("mov.b64 {%0, %1}, %2;" : "=f"(x), "=f"(y) : "l"(v));
    return make_float2(x, y);
}
__device__ __forceinline__ void ldsm4(uint32_t* r, uint32_t addr) {
    asm volatile("ldmatrix.sync.aligned.m8n8.x4.shared.b16 {%0,%1,%2,%3}, [%4];"
                 : "=r"(r[0]), "=r"(r[1]), "=r"(r[2]), "=r"(r[3]) : "r"(addr));
}
__device__ __forceinline__ void mma16816(float* d, const uint32_t* a,
                                         uint32_t b0, uint32_t b1) {
    asm volatile(
        "mma.sync.aligned.m16n8k16.row.col.f32.f16.f16.f32 "
        "{%0,%1,%2,%3}, {%4,%5,%6,%7}, {%8,%9}, {%0,%1,%2,%3};"
        : "+f"(d[0]), "+f"(d[1]), "+f"(d[2]), "+f"(d[3])
        : "r"(a[0]), "r"(a[1]), "r"(a[2]), "r"(a[3]), "r"(b0), "r"(b1));
}

struct Params {
    const float* inputs;   // [B*L] in {0,1}
    const int*   p;        // [L]
    const float* w[20];    // net0: wz0,bz0,wh0,bh0,wz1,bz1,wh1,bh1,wo,bo ; net1 same
    float*       out;      // [B*L*2]
};

// ---- shared memory layout (byte offsets) ----
#define OFF_A    0            // fp16 [128 m][72] (144 B rows)        18432
#define OFF_UNI  18432        // union: B tile (fp16 [64][72]) / ab float2[64][66] / fw
#define OFF_COMP 52224        // ulonglong2[8 grp][32 pair] = 4096
#define OFF_CR0  56320        // ull[2][32] = 512
#define OFF_CR1  56832        // ull[2][32] = 512
#define OFF_XS   57344        // uint32[2][2] packed x bits = 16
#define OFF_RED  57360        // float[16] / double[8] = 64
#define OFF_FLAG 57424        // float flag (+pad)
#define SMEM_BYTES 57440

#define AROW    144
#define ABSTR   66            // ab row stride in float2 (132 floats)

__global__ void __launch_bounds__(256, 4) gru_main_kernel(Params prm) {
    extern __shared__ char sm[];
    float2*     ab    = (float2*)(sm + OFF_UNI);     // [t*66 + j]
    float*      fw    = (float*)(sm + OFF_UNI);      // packed h*wo [t*132 + c]
    ulonglong2* comp2 = (ulonglong2*)(sm + OFF_COMP);// [grp*32 + pair]
    ull*        cr0p  = (ull*)(sm + OFF_CR0);        // [kb*32 + pair]
    ull*        cr1p  = (ull*)(sm + OFF_CR1);
    unsigned*   xsw   = (unsigned*)(sm + OFF_XS);    // [kb*2 + word]
    float*      red   = (float*)(sm + OFF_RED);
    double*     redd  = (double*)(sm + OFF_RED);
    float*      flag  = (float*)(sm + OFF_FLAG);

    const uint32_t smb = smem_u32(sm);
    const int tid  = threadIdx.x;
    const int wid  = tid >> 5;
    const int lane = tid & 31;
    const int b    = blockIdx.x >> 1;
    const int net  = blockIdx.x & 1;

    const float* const* w = prm.w + net * 10;

    // ---- A tile: interleaved rows (m=2j -> wz1 col j, m=2j+1 -> wh1 col j) ----
    for (int i = tid; i < 128 * 64; i += 256) {
        int m = i >> 6, c = i & 63;
        int j = m >> 1;
        float v = (m & 1) ? w[6][c * 64 + j] : w[4][c * 64 + j];
        *(__half*)(sm + OFF_A + m * AROW + 2 * c) = __float2half_rn(v);
    }
    if (tid < 64) {
        cr0p[tid] = 0ull;
        cr1p[tid] = 0ull;
    }
    // first x chunk -> ballot words (warps 0,1: t = wid*32 + lane)
    if (wid < 2) {
        int t = wid * 32 + lane;
        int src = net ? prm.p[t] : t;
        float xv = prm.inputs[(size_t)b * LL + src];
        unsigned m = __ballot_sync(0xffffffffu, xv > 0.5f);
        if (lane == 0) xsw[wid] = m;
    }

    // ---- packed per-thread scan constants (channel pair = lane) ----
    const int cpp = lane;                      // pair index: channels 2cpp, 2cpp+1
    const int grp = wid;                       // t-octet (warp-uniform)
    ull A0pk, B0pk, A1pk, B1pk, woc2;
    {
        int c0 = 2 * cpp, c1 = c0 + 1;
        float wza = w[0][c0], bza = w[1][c0], wha = w[2][c0], bha = w[3][c0];
        float wzb = w[0][c1], bzb = w[1][c1], whb = w[2][c1], bhb = w[3][c1];
        float z0a = sigmoidf(bza),       z0b = sigmoidf(bzb);
        float z1a = sigmoidf(wza + bza), z1b = sigmoidf(wzb + bzb);
        A0pk = pack2(1.0f - z0a, 1.0f - z0b);
        B0pk = pack2(z0a * bha, z0b * bhb);
        A1pk = pack2(1.0f - z1a, 1.0f - z1b);
        B1pk = pack2(z1a * (wha + bha), z1b * (whb + bhb));
        woc2 = pack2(w[8][c0], w[8][c1]);
    }
    const ull ONE2 = pack2(1.0f, 1.0f);
    const int xword  = grp >> 2;
    const int xshift = (grp & 3) * 8;

    // epilogue / projection roles (identical to R12)
    const int wm = wid >> 1;                   // m32n32 tiling
    const int wn = wid & 1;
    const int jb = 16 * wm + (lane >> 3);
    const float bo  = w[9][0];
    const bool  evn = ((lane >> 2) & 1) == 0;
    const int   etl = 2 * (lane & 3) + ((lane >> 2) & 1);
    const int   e_t = tid >> 2;
    const int   e_s = tid & 3;
    // chunk-invariant layer-1 biases (registers, no smem)
    const float2 biaA0 = make_float2(w[5][jb],      w[7][jb]);
    const float2 biaA4 = make_float2(w[5][jb + 4],  w[7][jb + 4]);
    const float2 biaB0 = make_float2(w[5][jb + 8],  w[7][jb + 8]);
    const float2 biaB4 = make_float2(w[5][jb + 12], w[7][jb + 12]);

    // ldmatrix per-lane base addresses (identical to R12)
    const uint32_t a_lane = smb + OFF_A + (32 * wm + (lane & 15)) * AROW
                            + (lane >> 4) * 16;
    const int brow = (lane & 7) + ((lane >> 4) << 3);
    const uint32_t b_lane = smb + OFF_UNI + (32 * wn + brow) * AROW
                            + ((lane >> 3) & 1) * 16;

    float lsum = 0.0f, lsq = 0.0f;
    __syncthreads();

    ull hl2[8], Pp2[8];

    for (int k = 0; k < NC; ++k) {
        const int kb = k & 1;

        // ===== layer-0 scan (binary gate, f32x2 packed: 2 ch x 8 t) =====
        {
            unsigned xw = xsw[kb * 2 + xword];
            ull h2 = 0ull, P2 = ONE2;
            #pragma unroll
            for (int i = 0; i < 8; ++i) {
                bool bit = (xw >> (xshift + i)) & 1u;
                ull a2 = bit ? A1pk : A0pk;
                ull b2 = bit ? B1pk : B0pk;
                h2 = fma2(a2, h2, b2);  hl2[i] = h2;
                P2 = mul2(P2, a2);      Pp2[i] = P2;
            }
            ulonglong2 cw;  cw.x = P2;  cw.y = h2;
            comp2[grp * 32 + cpp] = cw;                    // STS.128
            __syncthreads();                               // B1
            ull hin2 = cr0p[kb * 32 + cpp];
            #pragma unroll
            for (int qq = 0; qq < 7; ++qq) {
                if (qq < grp) {
                    ulonglong2 cc = comp2[qq * 32 + cpp];
                    hin2 = fma2(cc.x, hin2, cc.y);
                }
            }
            if (grp == 7) cr0p[(kb ^ 1) * 32 + cpp] = fma2(P2, hin2, h2);
            #pragma unroll
            for (int i = 0; i < 8; ++i) {
                float2 vf = unpack2(fma2(Pp2[i], hin2, hl2[i]));
                int t = grp * 8 + i;
                *(__half2*)(sm + OFF_UNI + t * AROW + 4 * cpp) =
                    __floats2half2_rn(vf.x, vf.y);
            }
        }
        __syncthreads();                                   // B2: B ready

        // ===== mma.sync m32n32: D = Ahi . Bhi^T, fp16, fp32 accum =====
        float acc[8][4];
        #pragma unroll
        for (int nt = 0; nt < 8; ++nt)
            #pragma unroll
            for (int q = 0; q < 4; ++q) acc[nt][q] = 0.0f;

        #pragma unroll
        for (int ks = 0; ks < 4; ++ks) {
            uint32_t a0[4], a1[4];
            ldsm4(a0, a_lane + ks * 32);
            ldsm4(a1, a_lane + 16 * AROW + ks * 32);
            #pragma unroll
            for (int g2 = 0; g2 < 2; ++g2) {
                uint32_t bb[4];
                ldsm4(bb, b_lane + g2 * (16 * AROW) + ks * 32);
                mma16816(acc[2 * g2],         a0, bb[0], bb[1]);
                mma16816(acc[2 * g2 + 1],     a0, bb[2], bb[3]);
                mma16816(acc[4 + 2 * g2],     a1, bb[0], bb[1]);
                mma16816(acc[4 + 2 * g2 + 1], a1, bb[2], bb[3]);
            }
        }
        // prefetch next x chunk -> ballot words
        if (wid < 2 && k + 1 < NC) {
            int t = (k + 1) * TT + wid * 32 + lane;
            int src = net ? prm.p[t] : t;
            unsigned m = __ballot_sync(0xffffffffu,
                                       prm.inputs[(size_t)b * LL + src] > 0.5f);
            if (lane == 0) xsw[(kb ^ 1) * 2 + wid] = m;
        }
        __syncthreads();                                   // B3: B free (-> ab)

        // ===== epilogue: pair z/htilde rows via shfl, gate -> ab =====
        #pragma unroll
        for (int mt = 0; mt < 2; ++mt) {
            const int j0 = jb + 8 * mt;
            const float2 bia0 = mt ? biaB0 : biaA0;
            const float2 bia4 = mt ? biaB4 : biaA4;
            #pragma unroll
            for (int g = 0; g < 4; ++g) {
                float* ac = acc[mt * 4 + g];
                float c0 = ac[0], c1 = ac[1], c2 = ac[2], c3 = ac[3];
                float p0 = __shfl_xor_sync(0xffffffffu, c0, 4);
                float p1 = __shfl_xor_sync(0xffffffffu, c1, 4);
                float p2 = __shfl_xor_sync(0xffffffffu, c2, 4);
                float p3 = __shfl_xor_sync(0xffffffffu, c3, 4);
                float z0 = evn ? c0 : p1;
                float h0 = evn ? p0 : c1;
                float z4 = evn ? c2 : p3;
                float h4 = evn ? p2 : c3;
                int t = 32 * wn + 8 * g + etl;
                // sigmoid(x) = 0.5*tanh(0.5x) + 0.5
                float t0  = tanh_fast(0.5f * (z0 + bia0.x));
                float t4t = tanh_fast(0.5f * (z4 + bia4.x));
                float a0v = fmaf(-0.5f, t0, 0.5f);
                float s0  = fmaf( 0.5f, t0, 0.5f);
                float a4v = fmaf(-0.5f, t4t, 0.5f);
                float s4  = fmaf( 0.5f, t4t, 0.5f);
                ab[t * ABSTR + j0]     = make_float2(a0v, s0 * (h0 + bia0.y));
                ab[t * ABSTR + j0 + 4] = make_float2(a4v, s4 * (h4 + bia4.y));
            }
        }
        __syncthreads();                                   // B4: ab ready

        // ===== layer-1 scan (f32x2 packed); fixup writes packed fw = h*wo ====
        {
            ull h2 = 0ull, P2 = ONE2;
            #pragma unroll
            for (int i = 0; i < 8; ++i) {
                int t = grp * 8 + i;
                float4 v = *(const float4*)&ab[t * ABSTR + 2 * cpp]; // a0,b0,a1,b1
                ull a2 = pack2(v.x, v.z);
                ull b2 = pack2(v.y, v.w);
                h2 = fma2(a2, h2, b2);  hl2[i] = h2;
                P2 = mul2(P2, a2);      Pp2[i] = P2;
            }
            ulonglong2 cw;  cw.x = P2;  cw.y = h2;
            comp2[grp * 32 + cpp] = cw;
            __syncthreads();                               // B5: ab reads done
            ull hin2 = cr1p[kb * 32 + cpp];
            #pragma unroll
            for (int qq = 0; qq < 7; ++qq) {
                if (qq < grp) {
                    ulonglong2 cc = comp2[qq * 32 + cpp];
                    hin2 = fma2(cc.x, hin2, cc.y);
                }
            }
            if (grp == 7) cr1p[(kb ^ 1) * 32 + cpp] = fma2(P2, hin2, h2);
            #pragma unroll
            for (int i = 0; i < 8; ++i) {
                ull r = mul2(fma2(Pp2[i], hin2, hl2[i]), woc2);
                int t = grp * 8 + i;
                *(ull*)&fw[t * 132 + 2 * cpp] = r;         // STS.64 packed
            }
        }
        __syncthreads();                                   // B6: fw ready

        // ===== output projection: 4 threads per t, packed float4 reads =====
        {
            const float* fr = fw + e_t * 132 + e_s * 16;
            float4 v0 = *(const float4*)(fr + 0);
            float4 v1 = *(const float4*)(fr + 4);
            float4 v2 = *(const float4*)(fr + 8);
            float4 v3 = *(const float4*)(fr + 12);
            float ssum = (v0.x + v0.y + v0.z + v0.w) + (v1.x + v1.y + v1.z + v1.w)
                       + (v2.x + v2.y + v2.z + v2.w) + (v3.x + v3.y + v3.z + v3.w);
            ssum += __shfl_xor_sync(0xffffffffu, ssum, 1);
            ssum += __shfl_xor_sync(0xffffffffu, ssum, 2);
            if (e_s == 0) {
                float o = ssum + bo;
                prm.out[((size_t)(b * LL + k * TT + e_t)) * 2 + net] = o;
                lsum += o;
                lsq  += o * o;
            }
        }
        // no B7: fw reads (pre-B1) vs next UNI writes (post-B1) ordered by B1
    }

    // ===== per-CTA stats -> g_part, then last CTA computes mean/rstd =====
    #pragma unroll
    for (int o = 16; o > 0; o >>= 1) {
        lsum += __shfl_down_sync(0xffffffffu, lsum, o);
        lsq  += __shfl_down_sync(0xffffffffu, lsq,  o);
    }
    if (lane == 0) {
        red[wid]     = lsum;
        red[8 + wid] = lsq;
    }
    __syncthreads();
    if (tid == 0) {
        float s = 0.0f, q = 0.0f;
        #pragma unroll
        for (int i = 0; i < 8; ++i) { s += red[i]; q += red[8 + i]; }
        g_part[blockIdx.x] = make_float2(s, q);
        __threadfence();
        unsigned prev = atomicAdd(&g_done, 1u);
        flag[0] = (prev == 2u * BB - 1u) ? 1.0f : 0.0f;
    }
    __syncthreads();
    if (flag[0] != 0.0f) {
        // last CTA: deterministic fixed-order reduction over g_part
        double s = 0.0, q = 0.0;
        for (int i = tid; i < 2 * BB; i += 256) {
            const volatile float* vp = (const volatile float*)&g_part[i];
            float vx = vp[0];
            float vy = vp[1];
            s += (double)vx;
            q += (double)vy;
        }
        #pragma unroll
        for (int o = 16; o > 0; o >>= 1) {
            s += __shfl_down_sync(0xffffffffu, s, o);
            q += __shfl_down_sync(0xffffffffu, q, o);
        }
        __syncthreads();                   // red[] float use above is done
        if (lane == 0) {
            redd[wid] = s;
            *(double*)(sm + OFF_CR0 + 8 * wid) = q;   // scratch (cr0 dead)
        }
        __syncthreads();
        if (tid == 0) {
            double ts = 0.0, tq = 0.0;
            #pragma unroll
            for (int i = 0; i < 8; ++i) {
                ts += redd[i];
                tq += *(double*)(sm + OFF_CR0 + 8 * i);
            }
            double n = (double)NTOT;
            double mean = ts / n;
            double var  = (tq - n * mean * mean) / (n - 1.0);
            g_mean_f = (float)mean;
            g_rstd_f = (float)(1.0 / sqrt(var));
            g_done = 0;                    // reset for next graph replay
        }
    }
}

__global__ void normalize_kernel(float4* out4) {
    float m  = g_mean_f;
    float rs = g_rstd_f;
    int i = blockIdx.x * blockDim.x + threadIdx.x;
    float4 v = out4[i];
    v.x = (v.x - m) * rs;
    v.y = (v.y - m) * rs;
    v.z = (v.z - m) * rs;
    v.w = (v.w - m) * rs;
    out4[i] = v;
}

extern "C" void kernel_launch(void* const* d_in, const int* in_sizes, int n_in,
                              void* d_out, int out_size) {
    (void)in_sizes; (void)n_in; (void)out_size;

    Params prm;
    prm.inputs = (const float*)d_in[0];
    prm.p      = (const int*)d_in[1];
    for (int i = 0; i < 20; ++i) {
        prm.w[i] = (const float*)d_in[2 + i];
    }
    prm.out = (float*)d_out;

    cudaFuncSetAttribute(gru_main_kernel,
                         cudaFuncAttributeMaxDynamicSharedMemorySize, SMEM_BYTES);

    gru_main_kernel<<<BB * 2, 256, SMEM_BYTES>>>(prm);
    normalize_kernel<<<(NTOT / 4) / 256, 256>>>((float4*)d_out);
}

// round 16
// speedup vs baseline: 1.2900x; 1.2900x over previous
#include <cuda_runtime.h>
#include <cuda_fp16.h>
#include <cstdint>

// ENC_GRUTurbo: fused 2-layer minGRU x2 nets + global standardize.
// B=256, L=2048, H=64. One CTA per (batch, net).
// R16 = R12 verbatim (best measured: 196.8us). fp16 single-plane mma.sync,
// m32n32 warp tiling, bitmask xs, packed fw, folded stats, 2 launches.

#define BB 256
#define LL 2048
#define HH 64
#define TT 64
#define QT 16
#define NC (LL / TT)
#define NTOT (BB * LL * 2)

__device__ float2 g_part[BB * 2];
__device__ float g_mean_f, g_rstd_f;
__device__ unsigned int g_done;   // reset to 0 by last CTA each launch

__device__ __forceinline__ uint32_t smem_u32(const void* p) {
    uint32_t a;
    asm("{ .reg .u64 t; cvta.to.shared.u64 t, %1; cvt.u32.u64 %0, t; }"
        : "=r"(a) : "l"(p));
    return a;
}
__device__ __forceinline__ float sigmoidf(float x) {       // precise (init only)
    return 1.0f / (1.0f + __expf(-x));
}
__device__ __forceinline__ float tanh_fast(float x) {      // hot path
    float t;
    asm("tanh.approx.f32 %0, %1;" : "=f"(t) : "f"(x));
    return t;
}
__device__ __forceinline__ void ldsm4(uint32_t* r, uint32_t addr) {
    asm volatile("ldmatrix.sync.aligned.m8n8.x4.shared.b16 {%0,%1,%2,%3}, [%4];"
                 : "=r"(r[0]), "=r"(r[1]), "=r"(r[2]), "=r"(r[3]) : "r"(addr));
}
__device__ __forceinline__ void mma16816(float* d, const uint32_t* a,
                                         uint32_t b0, uint32_t b1) {
    asm volatile(
        "mma.sync.aligned.m16n8k16.row.col.f32.f16.f16.f32 "
        "{%0,%1,%2,%3}, {%4,%5,%6,%7}, {%8,%9}, {%0,%1,%2,%3};"
        : "+f"(d[0]), "+f"(d[1]), "+f"(d[2]), "+f"(d[3])
        : "r"(a[0]), "r"(a[1]), "r"(a[2]), "r"(a[3]), "r"(b0), "r"(b1));
}

struct Params {
    const float* inputs;   // [B*L] in {0,1}
    const int*   p;        // [L]
    const float* w[20];    // net0: wz0,bz0,wh0,bh0,wz1,bz1,wh1,bh1,wo,bo ; net1 same
    float*       out;      // [B*L*2]
};

// ---- shared memory layout (byte offsets) ----
#define OFF_A    0            // fp16 [128 m][72] (144 B rows)        18432
#define OFF_UNI  18432        // union: B tile / ab float2[64][66] / fw / tab
#define OFF_BIAS 52224        // float2[64] (bz1, bh1)  512
#define OFF_WO   52736        // float[64]   256
#define OFF_COMP 52992        // float2[4][64] 2048
#define OFF_CR0  55040        // float[2][64]  512
#define OFF_CR1  55552        // float[2][64]  512
#define OFF_XS   56064        // uint32[2][2] packed x bits  16
#define OFF_RED  56576        // float[16] / double[8]  64
#define OFF_FLAG 56640        // float[1] last-CTA flag
#define SMEM_BYTES 56656

#define AROW    144
#define ABSTR   66            // ab row stride in float2 (132 floats)

__global__ void __launch_bounds__(256, 4) gru_main_kernel(Params prm) {
    extern __shared__ char sm[];
    float2*   ab   = (float2*)(sm + OFF_UNI);    // [t*66 + j]
    float*    fw   = (float*)(sm + OFF_UNI);     // packed h*wo [t*132 + c]
    float4*   tab  = (float4*)(sm + OFF_UNI);    // alias: read once pre-loop
    float2*   bias = (float2*)(sm + OFF_BIAS);
    float*    wo_s = (float*)(sm + OFF_WO);
    float2*   comp = (float2*)(sm + OFF_COMP);   // [q*64 + c]
    float*    cr0  = (float*)(sm + OFF_CR0);     // [kb*64 + c]
    float*    cr1  = (float*)(sm + OFF_CR1);
    unsigned* xsw  = (unsigned*)(sm + OFF_XS);   // [kb*2 + word]
    float*    red  = (float*)(sm + OFF_RED);
    double*   redd = (double*)(sm + OFF_RED);
    float*    flag = (float*)(sm + OFF_FLAG);

    const uint32_t smb = smem_u32(sm);
    const int tid  = threadIdx.x;
    const int wid  = tid >> 5;
    const int lane = tid & 31;
    const int b    = blockIdx.x >> 1;
    const int net  = blockIdx.x & 1;

    const float* const* w = prm.w + net * 10;

    // ---- A tile: interleaved rows (m=2j -> wz1 col j, m=2j+1 -> wh1 col j) ----
    for (int i = tid; i < 128 * 64; i += 256) {
        int m = i >> 6, c = i & 63;
        int j = m >> 1;
        float v = (m & 1) ? w[6][c * 64 + j] : w[4][c * 64 + j];
        *(__half*)(sm + OFF_A + m * AROW + 2 * c) = __float2half_rn(v);
    }
    if (tid < HH) {
        float wz = w[0][tid], bz = w[1][tid];
        float wh = w[2][tid], bh = w[3][tid];
        float z0 = sigmoidf(bz);
        float z1 = sigmoidf(wz + bz);          // fma(1,w,b) == w+b exactly
        float4 t4v;
        t4v.x = 1.0f - z0;  t4v.y = z0 * bh;
        t4v.z = 1.0f - z1;  t4v.w = z1 * (wh + bh);
        tab[tid]  = t4v;
        bias[tid] = make_float2(w[5][tid], w[7][tid]);
        wo_s[tid] = w[8][tid];
        cr0[tid] = 0.0f;  cr0[64 + tid] = 0.0f;
        cr1[tid] = 0.0f;  cr1[64 + tid] = 0.0f;
    }
    // first x chunk -> ballot words (warps 0,1: t = wid*32 + lane)
    if (wid < 2) {
        int t = wid * 32 + lane;
        int src = net ? prm.p[t] : t;
        float xv = prm.inputs[(size_t)b * LL + src];
        unsigned m = __ballot_sync(0xffffffffu, xv > 0.5f);
        if (lane == 0) xsw[wid] = m;
    }
    __syncthreads();

    // roles
    const int cqc = tid & 63;                  // scans: channel
    const int cqq = tid >> 6;                  // scans: quarter
    const int e_t = tid >> 2;                  // reduce: timestep
    const int e_s = tid & 3;                   // reduce: slice

    const float4 t4 = tab[cqc];                // gate table (reg-resident)
    __syncthreads();                           // tab alias dead -> UNI reusable

    // m32n32 warp tiling: warp covers m-tiles {2wm, 2wm+1} x t [32wn, 32wn+32)
    const int wm = wid >> 1;                   // 0..3
    const int wn = wid & 1;                    // 0..1
    const int jb = 16 * wm + (lane >> 3);      // j for mt=0 (mt=1 adds 8)
    const float bo  = w[9][0];
    const bool  evn = ((lane >> 2) & 1) == 0;
    const int   etl = 2 * (lane & 3) + ((lane >> 2) & 1);  // t offset in n8 tile
    const int   xsh = (cqq & 1) * 16;          // bit shift base for scan quarter

    // ldmatrix per-lane base addresses
    const uint32_t a_lane = smb + OFF_A + (32 * wm + (lane & 15)) * AROW
                            + (lane >> 4) * 16;
    const int brow = (lane & 7) + ((lane >> 4) << 3);
    const uint32_t b_lane = smb + OFF_UNI + (32 * wn + brow) * AROW
                            + ((lane >> 3) & 1) * 16;

    float lsum = 0.0f, lsq = 0.0f;

    for (int k = 0; k < NC; ++k) {
        const int kb = k & 1;

        // ===== layer-0 scan (binary gate via bitmask) -> B tile (fp16) =====
        float hl[QT], Pp[QT];
        {
            unsigned xw = xsw[kb * 2 + (cqq >> 1)];
            float h = 0.0f, P = 1.0f;
            #pragma unroll
            for (int i = 0; i < QT; ++i) {
                bool bit = (xw >> (xsh + i)) & 1u;
                float a  = bit ? t4.z : t4.x;
                float bb = bit ? t4.w : t4.y;
                h = fmaf(a, h, bb);  hl[i] = h;
                P = P * a;           Pp[i] = P;
            }
            comp[cqq * 64 + cqc] = make_float2(P, h);
            __syncthreads();                               // B1
            float hin = cr0[kb * 64 + cqc];
            #pragma unroll
            for (int qq = 0; qq < 3; ++qq) {
                if (qq < cqq) {
                    float2 cc = comp[qq * 64 + cqc];
                    hin = fmaf(cc.x, hin, cc.y);
                }
            }
            if (cqq == 3) cr0[(kb ^ 1) * 64 + cqc] = fmaf(P, hin, h);
            #pragma unroll
            for (int i = 0; i < QT; ++i) {
                float v = fmaf(Pp[i], hin, hl[i]);
                int t = cqq * QT + i;
                *(__half*)(sm + OFF_UNI + t * AROW + 2 * cqc) = __float2half_rn(v);
            }
        }
        __syncthreads();                                   // B2: B ready

        // ===== mma.sync m32n32: D = Ahi . Bhi^T, fp16, fp32 accum =====
        float acc[8][4];                                   // [mt*4 + g][4]
        #pragma unroll
        for (int nt = 0; nt < 8; ++nt)
            #pragma unroll
            for (int q = 0; q < 4; ++q) acc[nt][q] = 0.0f;

        #pragma unroll
        for (int ks = 0; ks < 4; ++ks) {
            uint32_t a0[4], a1[4];
            ldsm4(a0, a_lane + ks * 32);
            ldsm4(a1, a_lane + 16 * AROW + ks * 32);
            #pragma unroll
            for (int g2 = 0; g2 < 2; ++g2) {               // n16 groups
                uint32_t bb[4];
                ldsm4(bb, b_lane + g2 * (16 * AROW) + ks * 32);
                mma16816(acc[2 * g2],         a0, bb[0], bb[1]);
                mma16816(acc[2 * g2 + 1],     a0, bb[2], bb[3]);
                mma16816(acc[4 + 2 * g2],     a1, bb[0], bb[1]);
                mma16816(acc[4 + 2 * g2 + 1], a1, bb[2], bb[3]);
            }
        }
        // prefetch next x chunk -> ballot words
        if (wid < 2 && k + 1 < NC) {
            int t = (k + 1) * TT + wid * 32 + lane;
            int src = net ? prm.p[t] : t;
            unsigned m = __ballot_sync(0xffffffffu,
                                       prm.inputs[(size_t)b * LL + src] > 0.5f);
            if (lane == 0) xsw[(kb ^ 1) * 2 + wid] = m;
        }
        __syncthreads();                                   // B3: B free (-> ab)

        // ===== epilogue: pair z/htilde rows via shfl, gate -> ab =====
        #pragma unroll
        for (int mt = 0; mt < 2; ++mt) {
            const int j0 = jb + 8 * mt;
            const float2 bia0 = bias[j0];
            const float2 bia4 = bias[j0 + 4];
            #pragma unroll
            for (int g = 0; g < 4; ++g) {
                float* ac = acc[mt * 4 + g];
                float c0 = ac[0], c1 = ac[1], c2 = ac[2], c3 = ac[3];
                float p0 = __shfl_xor_sync(0xffffffffu, c0, 4);
                float p1 = __shfl_xor_sync(0xffffffffu, c1, 4);
                float p2 = __shfl_xor_sync(0xffffffffu, c2, 4);
                float p3 = __shfl_xor_sync(0xffffffffu, c3, 4);
                float z0 = evn ? c0 : p1;
                float h0 = evn ? p0 : c1;
                float z4 = evn ? c2 : p3;
                float h4 = evn ? p2 : c3;
                int t = 32 * wn + 8 * g + etl;
                // sigmoid(x) = 0.5*tanh(0.5x) + 0.5
                float t0  = tanh_fast(0.5f * (z0 + bia0.x));
                float t4t = tanh_fast(0.5f * (z4 + bia4.x));
                float a0v = fmaf(-0.5f, t0, 0.5f);         // 1 - z
                float s0  = fmaf( 0.5f, t0, 0.5f);         // z
                float a4v = fmaf(-0.5f, t4t, 0.5f);
                float s4  = fmaf( 0.5f, t4t, 0.5f);
                ab[t * ABSTR + j0]     = make_float2(a0v, s0 * (h0 + bia0.y));
                ab[t * ABSTR + j0 + 4] = make_float2(a4v, s4 * (h4 + bia4.y));
            }
        }
        __syncthreads();                                   // B4: ab ready

        // ===== layer-1 scan; fixup writes packed fw = h*wo =====
        {
            float h = 0.0f, P = 1.0f;
            #pragma unroll
            for (int i = 0; i < QT; ++i) {
                float2 v = ab[(cqq * QT + i) * ABSTR + cqc];
                h = fmaf(v.x, h, v.y);  hl[i] = h;
                P = P * v.x;            Pp[i] = P;
            }
            comp[cqq * 64 + cqc] = make_float2(P, h);
            __syncthreads();                               // B5: ab reads done
            float hin = cr1[kb * 64 + cqc];
            #pragma unroll
            for (int qq = 0; qq < 3; ++qq) {
                if (qq < cqq) {
                    float2 cc = comp[qq * 64 + cqc];
                    hin = fmaf(cc.x, hin, cc.y);
                }
            }
            if (cqq == 3) cr1[(kb ^ 1) * 64 + cqc] = fmaf(P, hin, h);
            float woc = wo_s[cqc];
            #pragma unroll
            for (int i = 0; i < QT; ++i) {
                float v = fmaf(Pp[i], hin, hl[i]);
                fw[(cqq * QT + i) * 132 + cqc] = v * woc;  // packed
            }
        }
        __syncthreads();                                   // B6: fw ready

        // ===== output projection: 4 threads per t, packed float4 reads =====
        {
            const float* fr = fw + e_t * 132 + e_s * 16;
            float4 v0 = *(const float4*)(fr + 0);
            float4 v1 = *(const float4*)(fr + 4);
            float4 v2 = *(const float4*)(fr + 8);
            float4 v3 = *(const float4*)(fr + 12);
            float ssum = (v0.x + v0.y + v0.z + v0.w) + (v1.x + v1.y + v1.z + v1.w)
                       + (v2.x + v2.y + v2.z + v2.w) + (v3.x + v3.y + v3.z + v3.w);
            ssum += __shfl_xor_sync(0xffffffffu, ssum, 1);
            ssum += __shfl_xor_sync(0xffffffffu, ssum, 2);
            if (e_s == 0) {
                float o = ssum + bo;
                prm.out[((size_t)(b * LL + k * TT + e_t)) * 2 + net] = o;
                lsum += o;
                lsq  += o * o;
            }
        }
        // no B7: fw reads (pre-B1) vs next UNI writes (post-B1) ordered by B1
    }

    // ===== per-CTA stats -> g_part, then last CTA computes mean/rstd =====
    #pragma unroll
    for (int o = 16; o > 0; o >>= 1) {
        lsum += __shfl_down_sync(0xffffffffu, lsum, o);
        lsq  += __shfl_down_sync(0xffffffffu, lsq,  o);
    }
    if (lane == 0) {
        red[wid]     = lsum;
        red[8 + wid] = lsq;
    }
    __syncthreads();
    if (tid == 0) {
        float s = 0.0f, q = 0.0f;
        #pragma unroll
        for (int i = 0; i < 8; ++i) { s += red[i]; q += red[8 + i]; }
        g_part[blockIdx.x] = make_float2(s, q);
        __threadfence();
        unsigned prev = atomicAdd(&g_done, 1u);
        flag[0] = (prev == 2u * BB - 1u) ? 1.0f : 0.0f;
    }
    __syncthreads();
    if (flag[0] != 0.0f) {
        // last CTA: deterministic fixed-order reduction over g_part
        double s = 0.0, q = 0.0;
        for (int i = tid; i < 2 * BB; i += 256) {
            const volatile float* vp = (const volatile float*)&g_part[i];
            float vx = vp[0];
            float vy = vp[1];
            s += (double)vx;
            q += (double)vy;
        }
        #pragma unroll
        for (int o = 16; o > 0; o >>= 1) {
            s += __shfl_down_sync(0xffffffffu, s, o);
            q += __shfl_down_sync(0xffffffffu, q, o);
        }
        __syncthreads();                   // red[] float use above is done
        if (lane == 0) {
            redd[wid] = s;
            *(double*)(sm + OFF_CR0 + 8 * wid) = q;   // scratch (cr0 dead)
        }
        __syncthreads();
        if (tid == 0) {
            double ts = 0.0, tq = 0.0;
            #pragma unroll
            for (int i = 0; i < 8; ++i) {
                ts += redd[i];
                tq += *(double*)(sm + OFF_CR0 + 8 * i);
            }
            double n = (double)NTOT;
            double mean = ts / n;
            double var  = (tq - n * mean * mean) / (n - 1.0);
            g_mean_f = (float)mean;
            g_rstd_f = (float)(1.0 / sqrt(var));
            g_done = 0;                    // reset for next graph replay
        }
    }
}

__global__ void normalize_kernel(float4* out4) {
    float m  = g_mean_f;
    float rs = g_rstd_f;
    int i = blockIdx.x * blockDim.x + threadIdx.x;
    float4 v = out4[i];
    v.x = (v.x - m) * rs;
    v.y = (v.y - m) * rs;
    v.z = (v.z - m) * rs;
    v.w = (v.w - m) * rs;
    out4[i] = v;
}

extern "C" void kernel_launch(void* const* d_in, const int* in_sizes, int n_in,
                              void* d_out, int out_size) {
    (void)in_sizes; (void)n_in; (void)out_size;

    Params prm;
    prm.inputs = (const float*)d_in[0];
    prm.p      = (const int*)d_in[1];
    for (int i = 0; i < 20; ++i) {
        prm.w[i] = (const float*)d_in[2 + i];
    }
    prm.out = (float*)d_out;

    cudaFuncSetAttribute(gru_main_kernel,
                         cudaFuncAttributeMaxDynamicSharedMemorySize, SMEM_BYTES);

    gru_main_kernel<<<BB * 2, 256, SMEM_BYTES>>>(prm);
    normalize_kernel<<<(NTOT / 4) / 256, 256>>>((float4*)d_out);
}